// round 3
// baseline (speedup 1.0000x reference)
#include <cuda_runtime.h>

// EfficientInteractionBilinear — fused SIMT fp32 baseline.
// out[n,u] = sum_{i,e} A[n,i,e] * W[e,i,u]
//   A[n,i,e] = sum_s rbf[n,i,s] * S[n,s,e]
//   S[n,s,e] = sum_k sph[n,s,k] * m2[n,k,e],  m2 scattered from m via (id_reduce, Kidx)

#define NSPH     16
#define KMAXC    16
#define EMB      64
#define INTERM   64
#define UOUT     128
#define M_TILE   32
#define NTHREADS 256
#define MAX_EDGES 65536

// device scratch (no allocations allowed)
__device__ int g_tri[MAX_EDGES * KMAXC];
__device__ int g_idx64;

// Detect whether index arrays are int64 or int32. For int64 (little-endian,
// small non-negative values) every odd 32-bit word of Kidx is zero; for int32
// Kidx contains nonzero odd words (slot indices 1,3,5,...).
__global__ void detect_idx_dtype(const int* __restrict__ kidx_words, int nt)
{
    if (blockIdx.x == 0 && threadIdx.x == 0) {
        int n = nt < 128 ? nt : 128;
        int flag = 1;
        for (int t = 0; t < n; ++t)
            if (kidx_words[2 * t + 1] != 0) { flag = 0; break; }
        g_idx64 = flag;
    }
}

__global__ void init_map(int ne)
{
    int idx = blockIdx.x * blockDim.x + threadIdx.x;
    if (idx < ne * KMAXC) g_tri[idx] = -1;
}

__global__ void scatter_map(const void* __restrict__ idr_raw,
                            const void* __restrict__ kidx_raw, int nt, int ne)
{
    int t = blockIdx.x * blockDim.x + threadIdx.x;
    if (t >= nt) return;
    long long e, k;
    if (g_idx64) {
        e = ((const long long*)idr_raw)[t];
        k = ((const long long*)kidx_raw)[t];
    } else {
        e = (long long)((const int*)idr_raw)[t];
        k = (long long)((const int*)kidx_raw)[t];
    }
    if (e >= 0 && e < ne && k >= 0 && k < KMAXC)
        g_tri[(int)e * KMAXC + (int)k] = t;
}

struct SmemLayout {
    float S[M_TILE][NSPH][EMB];   // 128 KB  per-edge S matrices
    float W[EMB][UOUT];           //  32 KB  W slice for current i
    float A[M_TILE][EMB];         //   8 KB  A chunk for current i
    float R[M_TILE][NSPH];        //   2 KB  rbf slice for current i
    float m2[KMAXC][EMB];         //   4 KB  staged neighbor rows (one edge)
    float sphE[NSPH][KMAXC];      //   1 KB  sph for one edge
    int   tri[M_TILE][KMAXC];     //   2 KB  triplet map for tile
};

__device__ __forceinline__ void cp_async16(void* smem_dst, const void* gmem_src)
{
    unsigned saddr = (unsigned)__cvta_generic_to_shared(smem_dst);
    asm volatile("cp.async.cg.shared.global [%0], [%1], 16;\n"
                 :: "r"(saddr), "l"(gmem_src));
}

__global__ __launch_bounds__(NTHREADS, 1)
void eib_main(const float* __restrict__ rbf, const float* __restrict__ sph,
              const float* __restrict__ m, const float* __restrict__ wgt,
              float* __restrict__ out, int ne)
{
    extern __shared__ char smem_raw[];
    SmemLayout& sm = *reinterpret_cast<SmemLayout*>(smem_raw);
    const int tid = threadIdx.x;
    const int edge0 = blockIdx.x * M_TILE;

    // stage triplet map for this tile
    for (int j = tid; j < M_TILE * KMAXC; j += NTHREADS) {
        int me = j >> 4;
        int n = edge0 + me;
        sm.tri[me][j & 15] = (n < ne) ? g_tri[n * KMAXC + (j & 15)] : -1;
    }
    __syncthreads();

    // ---------------- Phase A: S[me][s][e] = sum_k sph[s][k] * m2[k][e] ----
    const int pk = tid >> 4;          // 0..15 (serves as k for load, s for compute)
    const int pe = (tid & 15) * 4;    // e offset (float4)
    for (int me = 0; me < M_TILE; ++me) {
        int n = edge0 + me;
        {
            float4 v = make_float4(0.f, 0.f, 0.f, 0.f);
            int t = sm.tri[me][pk];
            if (t >= 0)
                v = *reinterpret_cast<const float4*>(&m[(size_t)t * EMB + pe]);
            *reinterpret_cast<float4*>(&sm.m2[pk][pe]) = v;
            sm.sphE[pk][tid & 15] = (n < ne)
                ? sph[(size_t)n * (NSPH * KMAXC) + pk * KMAXC + (tid & 15)] : 0.f;
        }
        __syncthreads();
        {
            float4 acc = make_float4(0.f, 0.f, 0.f, 0.f);
            #pragma unroll
            for (int k = 0; k < KMAXC; ++k) {
                float c = sm.sphE[pk][k];
                float4 mv = *reinterpret_cast<const float4*>(&sm.m2[k][pe]);
                acc.x += c * mv.x; acc.y += c * mv.y;
                acc.z += c * mv.z; acc.w += c * mv.w;
            }
            *reinterpret_cast<float4*>(&sm.S[me][pk][pe]) = acc;
        }
        __syncthreads();
    }

    // ---------------- Main loop over i: build A chunk, GEMM vs W_i ---------
    // GEMM thread tile: 4 edges x 4 units. Warp spans 16 edges x 32 units so
    // per-e unique smem traffic per warp is 64B (A) + 128B (W) -> crossbar-light.
    const int wid = tid >> 5, lane = tid & 31;
    const int wu = wid & 3, wm = wid >> 2;     // 4 warps along u, 2 along edges
    const int lu = lane & 7, lm = lane >> 3;
    const int me0 = (wm * 4 + lm) * 4;         // 0..28
    const int u0 = (wu * 8 + lu) * 4;          // 0..124
    const int ca_me = tid >> 3;                // computeA: edge 0..31
    const int ca_e = (tid & 7) * 8;            // computeA: e block

    float acc[4][4];
    #pragma unroll
    for (int j = 0; j < 4; ++j)
        #pragma unroll
        for (int t = 0; t < 4; ++t) acc[j][t] = 0.f;

    for (int i = 0; i < INTERM; ++i) {
        // async-stage W[:, i, :] (latency hidden behind computeA)
        #pragma unroll
        for (int r = 0; r < 8; ++r) {
            int jj = tid + r * NTHREADS;        // float4 index 0..2047
            int e = jj >> 5, u = (jj & 31) * 4;
            cp_async16(&sm.W[e][u], &wgt[((size_t)e * INTERM + i) * UOUT + u]);
        }
        asm volatile("cp.async.commit_group;\n" ::: "memory");

        // stage rbf[:, i, :]
        #pragma unroll
        for (int r = 0; r < 2; ++r) {
            int jj = tid + r * NTHREADS;
            int me = jj >> 4, s = jj & 15;
            int n = edge0 + me;
            sm.R[me][s] = (n < ne)
                ? rbf[(size_t)n * (INTERM * NSPH) + (size_t)i * NSPH + s] : 0.f;
        }
        __syncthreads();   // R ready (W still in flight)

        // A[me][e] = sum_s R[me][s] * S[me][s][e]
        {
            float4 r0 = make_float4(0,0,0,0), r1 = make_float4(0,0,0,0);
            #pragma unroll
            for (int s = 0; s < NSPH; ++s) {
                float c = sm.R[ca_me][s];
                float4 s0 = *reinterpret_cast<const float4*>(&sm.S[ca_me][s][ca_e]);
                float4 s1 = *reinterpret_cast<const float4*>(&sm.S[ca_me][s][ca_e + 4]);
                r0.x += c * s0.x; r0.y += c * s0.y; r0.z += c * s0.z; r0.w += c * s0.w;
                r1.x += c * s1.x; r1.y += c * s1.y; r1.z += c * s1.z; r1.w += c * s1.w;
            }
            *reinterpret_cast<float4*>(&sm.A[ca_me][ca_e]) = r0;
            *reinterpret_cast<float4*>(&sm.A[ca_me][ca_e + 4]) = r1;
        }
        asm volatile("cp.async.wait_group 0;\n" ::: "memory");
        __syncthreads();   // A and W ready

        // acc[4me][4u] += A[me0..+3][e] * W[e][u0..+3]
        #pragma unroll
        for (int eb = 0; eb < EMB; eb += 4) {
            float aM[4][4];
            #pragma unroll
            for (int j = 0; j < 4; ++j) {
                float4 av = *reinterpret_cast<const float4*>(&sm.A[me0 + j][eb]);
                aM[j][0] = av.x; aM[j][1] = av.y; aM[j][2] = av.z; aM[j][3] = av.w;
            }
            #pragma unroll
            for (int t = 0; t < 4; ++t) {
                float4 w = *reinterpret_cast<const float4*>(&sm.W[eb + t][u0]);
                #pragma unroll
                for (int j = 0; j < 4; ++j) {
                    acc[j][0] += aM[j][t] * w.x;
                    acc[j][1] += aM[j][t] * w.y;
                    acc[j][2] += aM[j][t] * w.z;
                    acc[j][3] += aM[j][t] * w.w;
                }
            }
        }
        __syncthreads();   // before W/A overwritten next i
    }

    #pragma unroll
    for (int j = 0; j < 4; ++j) {
        int n = edge0 + me0 + j;
        if (n < ne) {
            float4 o = make_float4(acc[j][0], acc[j][1], acc[j][2], acc[j][3]);
            *reinterpret_cast<float4*>(&out[(size_t)n * UOUT + u0]) = o;
        }
    }
}

extern "C" void kernel_launch(void* const* d_in, const int* in_sizes, int n_in,
                              void* d_out, int out_size)
{
    const float* rbf = (const float*)d_in[0];
    const float* sph = (const float*)d_in[1];
    const float* m   = (const float*)d_in[2];
    const float* wgt = (const float*)d_in[3];
    const void*  idr = d_in[4];
    const void*  kid = d_in[5];

    int ne = in_sizes[0] / (INTERM * NSPH);
    int nt = in_sizes[4];

    detect_idx_dtype<<<1, 32>>>((const int*)kid, nt);
    init_map<<<(ne * KMAXC + 255) / 256, 256>>>(ne);
    scatter_map<<<(nt + 255) / 256, 256>>>(idr, kid, nt, ne);

    // idempotent; first (non-captured) correctness call makes it stick
    cudaFuncSetAttribute(eib_main, cudaFuncAttributeMaxDynamicSharedMemorySize,
                         (int)sizeof(SmemLayout));

    int grid = (ne + M_TILE - 1) / M_TILE;
    eib_main<<<grid, NTHREADS, sizeof(SmemLayout)>>>(rbf, sph, m, wgt,
                                                     (float*)d_out, ne);
}

// round 11
// speedup vs baseline: 2.0532x; 2.0532x over previous
#include <cuda_runtime.h>
#include <cstdint>

// EfficientInteractionBilinear — fused mma.sync (tf32) version for base sm_103.
// out[n,u] = sum_{i,e} A[n,i,e] * W[e,i,u]
//   S[n,s,e] = sum_k sph[n,s,k]*m2[n,k,e]      (s_gen -> g_S scratch)
//   A[n,c]   = sum_s rbf[n,i,s]*S[n,s,e]       (producer warps, fp32)
//   out      = A @ Wk^T via mma.sync m16n8k8 tf32 (consumer warps)
// K = 4096 = 256 chunks of 16 (chunk q: eb=q>>5 selects 8-e block, pair=q&31
// selects i-pair; in-chunk k = il*8 + e_local).
// R11 fix: end-of-iteration __syncthreads so cp.async issues for chunk q never
// overlap other warps' reads of the same double-buffer slot (B(q) vs B(q-2),
// R(q+1) vs R(q-1)) — the race behind R10's 5.2e-2 rel_err.

#define NSPH   16
#define KMAXC  16
#define EMB    64
#define INTERM 64
#define UOUT   128
#define MAXE   50176

// ---------------- device scratch (allocations forbidden) ----------------
__device__ int      g_tri[MAXE * KMAXC];
__device__ int      g_idx64;
__device__ float    g_S[(size_t)MAXE * 1024];   // [n][s16][e64]
__device__ unsigned g_W[(size_t)256 * 2048];    // per chunk: B-fragment-order 8KB

// ---------------- helpers ----------------
__device__ __forceinline__ unsigned cvt_tf32(float f) {
    unsigned r; asm("cvt.rn.tf32.f32 %0, %1;" : "=r"(r) : "f"(f)); return r;
}
__device__ __forceinline__ void cp16(void* smem_dst, const void* gmem_src) {
    unsigned a = (unsigned)__cvta_generic_to_shared(smem_dst);
    asm volatile("cp.async.cg.shared.global [%0], [%1], 16;" :: "r"(a), "l"(gmem_src));
}
#define CP_COMMIT() asm volatile("cp.async.commit_group;" ::: "memory")
#define CP_WAIT(n)  asm volatile("cp.async.wait_group %0;" :: "n"(n) : "memory")

#define MMA(c, a, b) asm volatile( \
    "mma.sync.aligned.m16n8k8.row.col.f32.tf32.tf32.f32 " \
    "{%0,%1,%2,%3}, {%4,%5,%6,%7}, {%8,%9}, {%0,%1,%2,%3};" \
    : "+f"((c)[0]), "+f"((c)[1]), "+f"((c)[2]), "+f"((c)[3]) \
    : "r"((a).x), "r"((a).y), "r"((a).z), "r"((a).w), "r"((b).x), "r"((b).y))

// ---------------- prologue (validated R3) ----------------
__global__ void detect_idx_dtype(const int* __restrict__ kw, int nt)
{
    if (blockIdx.x == 0 && threadIdx.x == 0) {
        int n = nt < 128 ? nt : 128, f = 1;
        for (int t = 0; t < n; ++t) if (kw[2*t+1] != 0) { f = 0; break; }
        g_idx64 = f;
    }
}
__global__ void init_map(int ne)
{
    int i = blockIdx.x * blockDim.x + threadIdx.x;
    if (i < ne * KMAXC) g_tri[i] = -1;
}
__global__ void scatter_map(const void* idr, const void* kid, int nt, int ne)
{
    int t = blockIdx.x * blockDim.x + threadIdx.x;
    if (t >= nt) return;
    long long e, k;
    if (g_idx64) { e = ((const long long*)idr)[t]; k = ((const long long*)kid)[t]; }
    else         { e = ((const int*)idr)[t];       k = ((const int*)kid)[t]; }
    if (e >= 0 && e < ne && k >= 0 && k < KMAXC) g_tri[(int)e*KMAXC + (int)k] = t;
}

// ---------------- S = sph @ m2, one warp per edge (plain fp32) ----------------
__global__ __launch_bounds__(256) void s_gen(const float* __restrict__ sph,
                                             const float* __restrict__ m, int ne)
{
    __shared__ float sphs[8][256];
    int w = threadIdx.x >> 5, l = threadIdx.x & 31;
    int n = blockIdx.x * 8 + w;
    if (n >= ne) return;
    for (int j = l; j < 256; j += 32) sphs[w][j] = sph[(size_t)n*256 + j];
    int tmine = (l < KMAXC) ? g_tri[n*KMAXC + l] : -1;
    __syncwarp();
    float a0[16], a1[16];
    #pragma unroll
    for (int s = 0; s < 16; ++s) { a0[s] = 0.f; a1[s] = 0.f; }
    for (int k = 0; k < 16; ++k) {
        int t = __shfl_sync(0xFFFFFFFFu, tmine, k);
        float m0 = 0.f, m1 = 0.f;
        if (t >= 0) {
            float2 mv = *(const float2*)&m[(size_t)t*EMB + 2*l];
            m0 = mv.x; m1 = mv.y;
        }
        #pragma unroll
        for (int s = 0; s < 16; ++s) {
            float c = sphs[w][s*16 + k];
            a0[s] += c * m0; a1[s] += c * m1;
        }
    }
    #pragma unroll
    for (int s = 0; s < 16; ++s)
        *(float2*)&g_S[(size_t)n*1024 + s*64 + 2*l] = make_float2(a0[s], a1[s]);
}

// ---------------- W -> tf32 in B-fragment order per chunk ----------------
// chunk q: image = [j(16 n-tiles)][ks(2)][lane(32)][2 words] u32 = 8KB
// b0 = Wk[u=j*8+g8][K(e=eb*8+tg,     i=pair*2+ks)]
// b1 = Wk[u=j*8+g8][K(e=eb*8+tg+4,   i=pair*2+ks)]
__global__ void wstage(const float* __restrict__ wgt)
{
    int gid = blockIdx.x*256 + threadIdx.x;           // 262144 total
    int lane = gid & 31, ks = (gid >> 5) & 1, j = (gid >> 6) & 15, q = gid >> 10;
    int g8 = lane >> 2, tg = lane & 3;
    int eb = q >> 5, pair = q & 31;
    int u = j*8 + g8, i = pair*2 + ks;
    int e0 = eb*8 + tg, e1 = e0 + 4;
    unsigned w0 = cvt_tf32(wgt[((size_t)e0*INTERM + i)*UOUT + u]);
    unsigned w1 = cvt_tf32(wgt[((size_t)e1*INTERM + i)*UOUT + u]);
    *(uint2*)&g_W[(size_t)q*2048 + (size_t)((j*2 + ks)*32 + lane)*2] =
        make_uint2(w0, w1);
}

// ---------------- main fused kernel ----------------
// smem: A[2][8KB] | B[2][8KB] | R[2][128 rows x 144B]
#define SM_A0 0
#define SM_A1 8192
#define SM_B0 16384
#define SM_B1 24576
#define SM_R0 32768
#define SM_R1 51200
#define RSTRB 144
#define SMEMSZ 69632

__global__ __launch_bounds__(512, 1)
void eib_main(const float* __restrict__ rbf, float* __restrict__ out, int ne)
{
    extern __shared__ char sm[];
    const int tid = threadIdx.x;
    const int n0 = blockIdx.x * 128;

    // ---- consumer identity (tid < 256) ----
    const int cw = tid >> 5, cl = tid & 31;
    const int wm = cw >> 2, wn = cw & 3;
    const int cg8 = cl >> 2, ctg = cl & 3;
    const int cxr = (cg8 >> 1) & 3;
    float acc[4][4][4];
    #pragma unroll
    for (int a = 0; a < 4; ++a)
        #pragma unroll
        for (int b = 0; b < 4; ++b)
            #pragma unroll
            for (int c = 0; c < 4; ++c) acc[a][b][c] = 0.f;

    // ---- producer identity (tid >= 256) ----
    const int pt  = tid - 256;
    const int row = (pt >> 1) & 127, eh = pt & 1;
    const int pm = row >> 4, r16 = row & 15;
    const int pg8 = r16 & 7, phi = r16 >> 3;
    const int pword = phi + 2*eh;
    const int pxr = (pg8 >> 1) & 3;
    const int nrc = (n0 + row < ne) ? (n0 + row) : (ne - 1);
    float S2[16][4];

    // pre-issue R(0)
    {
        char* dst = sm + SM_R0;
        #pragma unroll
        for (int r = 0; r < 2; ++r) {
            int seg = tid*2 + r;                   // 0..1023
            int rw = seg >> 3, part = seg & 7;
            int n = (n0 + rw < ne) ? (n0 + rw) : (ne - 1);
            cp16(dst + rw*RSTRB + part*16, &rbf[(size_t)n*1024 + part*4]);
        }
        CP_COMMIT();
    }

    for (int q = 0; q <= 256; ++q) {
        if (q < 256) {           // issue B(q)
            char* dst = sm + ((q & 1) ? SM_B1 : SM_B0);
            cp16(dst + tid*16, (const char*)g_W + (size_t)q*8192 + tid*16);
            CP_COMMIT();
        }
        if (q + 1 < 256) {       // issue R(q+1)
            char* dst = sm + (((q+1) & 1) ? SM_R1 : SM_R0);
            int pair = (q + 1) & 31;
            #pragma unroll
            for (int r = 0; r < 2; ++r) {
                int seg = tid*2 + r;
                int rw = seg >> 3, part = seg & 7;
                int n = (n0 + rw < ne) ? (n0 + rw) : (ne - 1);
                cp16(dst + rw*RSTRB + part*16,
                     &rbf[(size_t)n*1024 + pair*32 + part*4]);
            }
            CP_COMMIT();
        }
        if (q < 255)       CP_WAIT(2);   // R(q), B(q-1) done
        else if (q == 255) CP_WAIT(1);   // R(255), B(254) done
        else               CP_WAIT(0);   // B(255) done
        __syncthreads();

        if (tid < 256) {
            // -------- consumers: mma chunk q-1 --------
            if (q >= 1) {
                const char* Ab = sm + (((q-1) & 1) ? SM_A1 : SM_A0);
                const char* Bb = sm + (((q-1) & 1) ? SM_B1 : SM_B0);
                #pragma unroll
                for (int ks = 0; ks < 2; ++ks) {
                    uint4 af[4];
                    #pragma unroll
                    for (int mt = 0; mt < 4; ++mt)
                        af[mt] = *(const uint4*)(Ab +
                            ((((wm*4 + mt)*2 + ks)*32 + cg8*4 + (ctg ^ cxr)) << 4));
                    uint2 bf[4];
                    #pragma unroll
                    for (int nt = 0; nt < 4; ++nt)
                        bf[nt] = *(const uint2*)(Bb +
                            ((((wn*4 + nt)*2 + ks)*32 + cl) << 3));
                    #pragma unroll
                    for (int mt = 0; mt < 4; ++mt)
                        #pragma unroll
                        for (int nt = 0; nt < 4; ++nt)
                            MMA(acc[mt][nt], af[mt], bf[nt]);
                }
            }
        } else if (q < 256) {
            // -------- producers: A-gen chunk q --------
            if ((q & 31) == 0) {   // reload S slice for new e-block
                int eb = q >> 5;
                const float* sp = &g_S[(size_t)nrc*1024 + eb*8 + eh*4];
                #pragma unroll
                for (int s = 0; s < 16; ++s) {
                    float4 v = *(const float4*)(sp + s*64);
                    S2[s][0] = v.x; S2[s][1] = v.y; S2[s][2] = v.z; S2[s][3] = v.w;
                }
            }
            const char* Rb = sm + ((q & 1) ? SM_R1 : SM_R0) + row*RSTRB;
            float pacc[2][4];
            #pragma unroll
            for (int il = 0; il < 2; ++il)
                #pragma unroll
                for (int e = 0; e < 4; ++e) pacc[il][e] = 0.f;
            #pragma unroll
            for (int il = 0; il < 2; ++il)
                #pragma unroll
                for (int part = 0; part < 4; ++part) {
                    float4 rv = *(const float4*)(Rb + il*64 + part*16);
                    float rr[4] = {rv.x, rv.y, rv.z, rv.w};
                    #pragma unroll
                    for (int w = 0; w < 4; ++w) {
                        int s = part*4 + w;
                        #pragma unroll
                        for (int e = 0; e < 4; ++e)
                            pacc[il][e] += rr[w] * S2[s][e];
                    }
                }
            char* Ab = sm + ((q & 1) ? SM_A1 : SM_A0);
            #pragma unroll
            for (int il = 0; il < 2; ++il)
                #pragma unroll
                for (int e = 0; e < 4; ++e) {
                    int slot = (pm*2 + il)*32 + pg8*4 + (e ^ pxr);
                    *(unsigned*)(Ab + slot*16 + pword*4) = cvt_tf32(pacc[il][e]);
                }
        }
        // R11 FIX: drain all reads of this iteration's buffers before any
        // thread issues next iteration's cp.async into the sibling slots.
        __syncthreads();
    }

    // -------- epilogue: consumers store acc --------
    if (tid < 256) {
        #pragma unroll
        for (int mt = 0; mt < 4; ++mt)
            #pragma unroll
            for (int nt = 0; nt < 4; ++nt) {
                int r0 = wm*64 + mt*16 + cg8;
                int u0 = wn*32 + nt*8 + ctg*2;
                if (n0 + r0 < ne)
                    *(float2*)&out[(size_t)(n0 + r0)*UOUT + u0] =
                        make_float2(acc[mt][nt][0], acc[mt][nt][1]);
                if (n0 + r0 + 8 < ne)
                    *(float2*)&out[(size_t)(n0 + r0 + 8)*UOUT + u0] =
                        make_float2(acc[mt][nt][2], acc[mt][nt][3]);
            }
    }
}

extern "C" void kernel_launch(void* const* d_in, const int* in_sizes, int n_in,
                              void* d_out, int out_size)
{
    const float* rbf = (const float*)d_in[0];
    const float* sph = (const float*)d_in[1];
    const float* m   = (const float*)d_in[2];
    const float* wgt = (const float*)d_in[3];
    const void*  idr = d_in[4];
    const void*  kid = d_in[5];
    int ne = in_sizes[0] / (INTERM * NSPH);
    int nt = in_sizes[4];

    detect_idx_dtype<<<1, 32>>>((const int*)kid, nt);
    init_map<<<(ne*KMAXC + 255)/256, 256>>>(ne);
    scatter_map<<<(nt + 255)/256, 256>>>(idr, kid, nt, ne);
    s_gen<<<(ne + 7)/8, 256>>>(sph, m, ne);
    wstage<<<1024, 256>>>(wgt);

    cudaFuncSetAttribute(eib_main, cudaFuncAttributeMaxDynamicSharedMemorySize, SMEMSZ);
    eib_main<<<(ne + 127)/128, 512, SMEMSZ>>>(rbf, (float*)d_out, ne);
}